// round 12
// baseline (speedup 1.0000x reference)
#include <cuda_runtime.h>
#include <cuda_bf16.h>
#include <cstdint>

// GAT-style structured attention, M=50000, L=32, F=128.
// R12 = R9 (per-thread cp.async.cg double-buffered staging -- highest
// measured BW of any variant, 6.5 TB/s) + R10's waste fix (no dead last-row
// prefetch). TMA bulk variant (R10/R11) reverted: 1024 independent 128B
// LDGSTS requests give more MLP than one 16KB bulk copy per CTA.
// Empty commit_group when no prefetch keeps wait_group 1 semantics.

#define L_SEG 32
#define F_DIM 128
#define TPB   256
#define WARPS (TPB / 32)          // 8
#define SPW   (L_SEG / WARPS)     // 4 segments per warp
#define ROWS_PER_CTA 8

__device__ __forceinline__ void cp_async16(void* smem_dst, const void* gsrc) {
    const unsigned s = (unsigned)__cvta_generic_to_shared(smem_dst);
    asm volatile("cp.async.cg.shared.global [%0], [%1], 16;" :: "r"(s), "l"(gsrc));
}

__global__ __launch_bounds__(TPB, 5)
void gat_row_kernel(const float* __restrict__ x,
                    const float* __restrict__ a,
                    float* __restrict__ out,
                    int M)
{
    const int tid  = threadIdx.x;
    const int w    = tid >> 5;
    const int lane = tid & 31;
    const int m0   = blockIdx.x * ROWS_PER_CTA;
    if (m0 >= M) return;
    const int rows = (M - m0 < ROWS_PER_CTA) ? (M - m0) : ROWS_PER_CTA;

    __shared__ float4 stage[2][TPB * SPW];       // 2 x 16KB staging
    __shared__ float  s_nbr[L_SEG];
    __shared__ float  s_msk[L_SEG];
    __shared__ float  warp_self[WARPS];          // 8 floats, float4-aligned
    __shared__ float4 hp[WARPS * 32];

    // ---- per-thread weight slices, loaded ONCE, reused for all rows ----
    const float4* __restrict__ a1p = (const float4*)a;
    float4 a1r[SPW];
#pragma unroll
    for (int j = 0; j < SPW; ++j)
        a1r[j] = __ldg(a1p + (w * SPW + j) * (F_DIM / 4) + lane);
    const float4 a2 = __ldg(((const float4*)(a + L_SEG * F_DIM)) + lane);

    const int seg_off = w * SPW * (F_DIM / 4) + lane;   // float4 units

    const bool b4 = (lane & 16) != 0;
    const bool b3 = (lane & 8)  != 0;
    const bool b2 = (lane & 4)  != 0;

    // ---- prologue: stage first row into buf 0 ----
    {
        const float4* __restrict__ xr =
            (const float4*)(x + (size_t)m0 * (L_SEG * F_DIM));
#pragma unroll
        for (int j = 0; j < SPW; ++j)
            cp_async16(&stage[0][j * TPB + tid], xr + seg_off + j * (F_DIM / 4));
        asm volatile("cp.async.commit_group;");
    }

#pragma unroll 1
    for (int r = 0; r < rows; ++r) {
        const int m = m0 + r;
        const int b = r & 1;

        // ---- stage NEXT row into the other buffer (only if consumed) ----
        if (r + 1 < rows) {
            const float4* __restrict__ xr =
                (const float4*)(x + (size_t)(m + 1) * (L_SEG * F_DIM));
#pragma unroll
            for (int j = 0; j < SPW; ++j)
                cp_async16(&stage[b ^ 1][j * TPB + tid],
                           xr + seg_off + j * (F_DIM / 4));
        }
        // commit unconditionally (possibly empty group) so wait_group 1
        // always means "row r's group has landed".
        asm volatile("cp.async.commit_group;");
        asm volatile("cp.async.wait_group 1;");

        // ---- pull this row from smem into registers (conflict-free) ----
        float4 v[SPW];
#pragma unroll
        for (int j = 0; j < SPW; ++j)
            v[j] = stage[b][j * TPB + tid];

        // ---- phase A: lane-local dots ----
        float sn[SPW], mk[SPW];
        float self_part = 0.f;
#pragma unroll
        for (int j = 0; j < SPW; ++j) {
            const float4 vv = v[j];
            mk[j] = (vv.x + vv.y) + (vv.z + vv.w);
            sn[j] = vv.x * a2.x + vv.y * a2.y + vv.z * a2.z + vv.w * a2.w;
            self_part += vv.x * a1r[j].x + vv.y * a1r[j].y
                       + vv.z * a1r[j].z + vv.w * a1r[j].w;
        }

        // ---- 8-value multi-butterfly (idx = lane>>2 at the end) ----
        float t0, t1, t2, t3;
        {
            const float s0 = b4 ? sn[0] : mk[0];
            const float s1 = b4 ? sn[1] : mk[1];
            const float s2 = b4 ? sn[2] : mk[2];
            const float s3 = b4 ? sn[3] : mk[3];
            t0 = (b4 ? mk[0] : sn[0]) + __shfl_xor_sync(0xffffffffu, s0, 16);
            t1 = (b4 ? mk[1] : sn[1]) + __shfl_xor_sync(0xffffffffu, s1, 16);
            t2 = (b4 ? mk[2] : sn[2]) + __shfl_xor_sync(0xffffffffu, s2, 16);
            t3 = (b4 ? mk[3] : sn[3]) + __shfl_xor_sync(0xffffffffu, s3, 16);
        }
        float u0, u1;
        {
            const float s0 = b3 ? t0 : t2;
            const float s1 = b3 ? t1 : t3;
            u0 = (b3 ? t2 : t0) + __shfl_xor_sync(0xffffffffu, s0, 8);
            u1 = (b3 ? t3 : t1) + __shfl_xor_sync(0xffffffffu, s1, 8);
        }
        float c;
        {
            const float s0 = b2 ? u0 : u1;
            c = (b2 ? u1 : u0) + __shfl_xor_sync(0xffffffffu, s0, 4);
        }
        c += __shfl_xor_sync(0xffffffffu, c, 2);
        c += __shfl_xor_sync(0xffffffffu, c, 1);

        // self-score: plain 5-level tree (independent chain)
#pragma unroll
        for (int o = 16; o; o >>= 1)
            self_part += __shfl_xor_sync(0xffffffffu, self_part, o);

        if ((lane & 3) == 0) {
            const int idx = lane >> 2;            // 0..7
            if (idx < 4) s_nbr[w * SPW + idx] = c;
            else         s_msk[w * SPW + (idx - 4)] = c;
        }
        if (lane == 0) warp_self[w] = self_part;
        __syncthreads();

        // ---- phase B: softmax over 32 segments (no max-subtraction) ----
        const float4 ws0 = ((const float4*)warp_self)[0];
        const float4 ws1 = ((const float4*)warp_self)[1];
        const float s_self = ((ws0.x + ws0.y) + (ws0.z + ws0.w))
                           + ((ws1.x + ws1.y) + (ws1.z + ws1.w));
        const float z = s_self + s_nbr[lane];
        float e = (z >= 0.0f) ? z : 0.2f * z;
        e = (s_msk[lane] != 0.0f) ? e : -1e30f;
        const float ex = __expf(e);               // masked -> 0
        float sum = ex;
#pragma unroll
        for (int o = 16; o; o >>= 1)
            sum += __shfl_xor_sync(0xffffffffu, sum, o);
        const float att_lane = ex / sum;

        // ---- attention-weighted recombination from registers ----
        float4 h = make_float4(0.f, 0.f, 0.f, 0.f);
#pragma unroll
        for (int j = 0; j < SPW; ++j) {
            const float aL = __shfl_sync(0xffffffffu, att_lane, w * SPW + j);
            h.x += aL * v[j].x;
            h.y += aL * v[j].y;
            h.z += aL * v[j].z;
            h.w += aL * v[j].w;
        }

        hp[w * 32 + lane] = h;
        __syncthreads();

        // ---- cross-warp reduce (warp 0) + epilogue + store ----
        if (w == 0) {
            float4 acc = hp[lane];
#pragma unroll
            for (int i = 1; i < WARPS; ++i) {
                const float4 t = hp[i * 32 + lane];
                acc.x += t.x; acc.y += t.y; acc.z += t.z; acc.w += t.w;
            }
            acc.x = (acc.x > 0.f) ? acc.x : (__expf(acc.x) - 1.0f);
            acc.y = (acc.y > 0.f) ? acc.y : (__expf(acc.y) - 1.0f);
            acc.z = (acc.z > 0.f) ? acc.z : (__expf(acc.z) - 1.0f);
            acc.w = (acc.w > 0.f) ? acc.w : (__expf(acc.w) - 1.0f);
            ((float4*)(out + (size_t)m * F_DIM))[lane] = acc;
        }
    }
}

extern "C" void kernel_launch(void* const* d_in, const int* in_sizes, int n_in,
                              void* d_out, int out_size)
{
    const float* x = (const float*)d_in[0];
    const float* a = (const float*)d_in[1];
    float* out = (float*)d_out;

    // Shapes from element counts (capture-safe):
    //   in_sizes[0] = M*L*F, in_sizes[1] = F*(L+1), out_size = M*F
    const long long total = in_sizes[0];
    const int L = (int)(total / (long long)out_size);      // 32
    const int F = in_sizes[1] / (L + 1);                   // 128
    const int M = out_size / F;                            // 50000
    (void)L; (void)F;

    const int grid = (M + ROWS_PER_CTA - 1) / ROWS_PER_CTA;
    gat_row_kernel<<<grid, TPB>>>(x, a, out, M);
}

// round 13
// speedup vs baseline: 1.0704x; 1.0704x over previous
#include <cuda_runtime.h>
#include <cuda_bf16.h>
#include <cstdint>

// GAT-style structured attention, M=50000, L=32, F=128.
// R13 = R10 base (TMA bulk staging, waste-fixed, ROWS=8 -- best so far)
// + early re-issue ONLY (R11's ROWS=16 reverted; that was the regression):
//   prologue stages rows 0+1; after row r's phase-A barrier (buffer b
//   drained) issue row r+2 into b -> >=1 TMA always in flight.
// + each row staged as 2x8KB bulk copies to one mbarrier (expect_tx
//   accumulates) for 2x request-level MLP.

#define L_SEG 32
#define F_DIM 128
#define TPB   256
#define WARPS (TPB / 32)          // 8
#define SPW   (L_SEG / WARPS)     // 4 segments per warp
#define ROWS_PER_CTA 8
#define ROW_BYTES (L_SEG * F_DIM * 4)   // 16384
#define HALF_BYTES (ROW_BYTES / 2)      // 8192

#define MBARRIER_INIT(addr, cnt) \
    asm volatile("mbarrier.init.shared.b64 [%0], %1;" :: "r"(addr), "r"(cnt) : "memory")
#define MBARRIER_EXPECT_TX(addr, bytes) \
    asm volatile("mbarrier.arrive.expect_tx.shared.b64 _, [%0], %1;" :: "r"(addr), "r"(bytes) : "memory")
#define MBARRIER_WAIT_PARITY(addr, parity) do {                                   \
    uint32_t _mb = (addr); uint32_t _p = (parity); uint32_t _done;                \
    asm volatile("{\n\t.reg .pred p;\n\t"                                         \
        "mbarrier.try_wait.parity.acquire.cta.shared::cta.b64 p, [%1], %2;\n\t"   \
        "selp.b32 %0, 1, 0, p;\n\t}"                                              \
        : "=r"(_done) : "r"(_mb), "r"(_p) : "memory");                            \
    if (!_done) {                                                                 \
        asm volatile("{\n\t.reg .pred P1;\n\t"                                    \
            "WL_%=:\n\t"                                                          \
            "mbarrier.try_wait.parity.acquire.cta.shared::cta.b64 P1, [%0], %1, 0x989680;\n\t" \
            "@P1 bra.uni WD_%=;\n\t"                                              \
            "bra.uni WL_%=;\n\t"                                                  \
            "WD_%=:\n\t}"                                                         \
            :: "r"(_mb), "r"(_p) : "memory");                                     \
    }                                                                             \
} while (0)

__device__ __forceinline__ void bulk_ldgsts(uint32_t smem_dst, const void* gsrc,
                                            uint32_t bytes, uint32_t mbar) {
    asm volatile(
        "cp.async.bulk.shared::cluster.global.mbarrier::complete_tx::bytes "
        "[%0], [%1], %2, [%3];"
        :: "r"(smem_dst), "l"(gsrc), "r"(bytes), "r"(mbar) : "memory");
}

// stage one row as two 8KB bulk copies (2x request MLP)
__device__ __forceinline__ void stage_row(uint32_t smem_dst, const float* gsrc,
                                          uint32_t mbar) {
    MBARRIER_EXPECT_TX(mbar, (uint32_t)ROW_BYTES);
    bulk_ldgsts(smem_dst, gsrc, (uint32_t)HALF_BYTES, mbar);
    bulk_ldgsts(smem_dst + (uint32_t)HALF_BYTES,
                (const char*)gsrc + HALF_BYTES, (uint32_t)HALF_BYTES, mbar);
}

__global__ __launch_bounds__(TPB, 5)
void gat_row_kernel(const float* __restrict__ x,
                    const float* __restrict__ a,
                    float* __restrict__ out,
                    int M)
{
    const int tid  = threadIdx.x;
    const int w    = tid >> 5;
    const int lane = tid & 31;
    const int m0   = blockIdx.x * ROWS_PER_CTA;
    if (m0 >= M) return;
    const int rows = (M - m0 < ROWS_PER_CTA) ? (M - m0) : ROWS_PER_CTA;

    __shared__ alignas(16) float4 stage[2][TPB * SPW];   // 2 x 16KB
    __shared__ alignas(8) unsigned long long mbar[2];
    __shared__ float  s_nbr[L_SEG];
    __shared__ float  s_msk[L_SEG];
    __shared__ float  warp_self[WARPS];                  // float4-aligned
    __shared__ float4 hp[WARPS * 32];

    const uint32_t mbar_u32  = (uint32_t)__cvta_generic_to_shared(&mbar[0]);
    const uint32_t stage_u32 = (uint32_t)__cvta_generic_to_shared(&stage[0][0]);

    if (tid == 0) {
        MBARRIER_INIT(mbar_u32, 1);
        MBARRIER_INIT(mbar_u32 + 8, 1);
    }
    __syncthreads();   // mbarrier init visible

    // ---- prologue: stage rows 0 and 1 (issuer: warp 7 lane 0) ----
    if (tid == TPB - 32) {
        stage_row(stage_u32, x + (size_t)m0 * (L_SEG * F_DIM), mbar_u32);
        if (rows > 1)
            stage_row(stage_u32 + (uint32_t)ROW_BYTES,
                      x + (size_t)(m0 + 1) * (L_SEG * F_DIM), mbar_u32 + 8);
    }

    // ---- per-thread weight slices (LDG latency overlaps the TMAs) ----
    const float4* __restrict__ a1p = (const float4*)a;
    float4 a1r[SPW];
#pragma unroll
    for (int j = 0; j < SPW; ++j)
        a1r[j] = __ldg(a1p + (w * SPW + j) * (F_DIM / 4) + lane);
    const float4 a2 = __ldg(((const float4*)(a + L_SEG * F_DIM)) + lane);

    const bool b4 = (lane & 16) != 0;
    const bool b3 = (lane & 8)  != 0;
    const bool b2 = (lane & 4)  != 0;

    int ph0 = 0, ph1 = 0;

#pragma unroll 1
    for (int r = 0; r < rows; ++r) {
        const int m = m0 + r;
        const int b = r & 1;

        // ---- wait for row r's data ----
        if (b == 0) { MBARRIER_WAIT_PARITY(mbar_u32,     ph0); ph0 ^= 1; }
        else        { MBARRIER_WAIT_PARITY(mbar_u32 + 8, ph1); ph1 ^= 1; }

        // ---- pull this row from smem (linear layout, conflict-free) ----
        float4 v[SPW];
#pragma unroll
        for (int j = 0; j < SPW; ++j)
            v[j] = stage[b][(w * SPW + j) * (F_DIM / 4) + lane];

        // ---- phase A: lane-local dots ----
        float sn[SPW], mk[SPW];
        float self_part = 0.f;
#pragma unroll
        for (int j = 0; j < SPW; ++j) {
            const float4 vv = v[j];
            mk[j] = (vv.x + vv.y) + (vv.z + vv.w);
            sn[j] = vv.x * a2.x + vv.y * a2.y + vv.z * a2.z + vv.w * a2.w;
            self_part += vv.x * a1r[j].x + vv.y * a1r[j].y
                       + vv.z * a1r[j].z + vv.w * a1r[j].w;
        }

        // ---- 8-value multi-butterfly (idx = lane>>2 at the end) ----
        float t0, t1, t2, t3;
        {
            const float s0 = b4 ? sn[0] : mk[0];
            const float s1 = b4 ? sn[1] : mk[1];
            const float s2 = b4 ? sn[2] : mk[2];
            const float s3 = b4 ? sn[3] : mk[3];
            t0 = (b4 ? mk[0] : sn[0]) + __shfl_xor_sync(0xffffffffu, s0, 16);
            t1 = (b4 ? mk[1] : sn[1]) + __shfl_xor_sync(0xffffffffu, s1, 16);
            t2 = (b4 ? mk[2] : sn[2]) + __shfl_xor_sync(0xffffffffu, s2, 16);
            t3 = (b4 ? mk[3] : sn[3]) + __shfl_xor_sync(0xffffffffu, s3, 16);
        }
        float u0, u1;
        {
            const float s0 = b3 ? t0 : t2;
            const float s1 = b3 ? t1 : t3;
            u0 = (b3 ? t2 : t0) + __shfl_xor_sync(0xffffffffu, s0, 8);
            u1 = (b3 ? t3 : t1) + __shfl_xor_sync(0xffffffffu, s1, 8);
        }
        float c;
        {
            const float s0 = b2 ? u0 : u1;
            c = (b2 ? u1 : u0) + __shfl_xor_sync(0xffffffffu, s0, 4);
        }
        c += __shfl_xor_sync(0xffffffffu, c, 2);
        c += __shfl_xor_sync(0xffffffffu, c, 1);

        // self-score: plain 5-level tree (independent chain)
#pragma unroll
        for (int o = 16; o; o >>= 1)
            self_part += __shfl_xor_sync(0xffffffffu, self_part, o);

        if ((lane & 3) == 0) {
            const int idx = lane >> 2;            // 0..7
            if (idx < 4) s_nbr[w * SPW + idx] = c;
            else         s_msk[w * SPW + (idx - 4)] = c;
        }
        if (lane == 0) warp_self[w] = self_part;
        __syncthreads();
        // ^ also proves every warp has drained stage[b]: reusable now.

        // ---- early re-issue: row r+2 into buffer b ----
        if (tid == TPB - 32 && r + 2 < rows)
            stage_row(stage_u32 + (uint32_t)(b * ROW_BYTES),
                      x + (size_t)(m + 2) * (L_SEG * F_DIM),
                      mbar_u32 + (uint32_t)(b * 8));

        // ---- phase B: softmax over 32 segments (no max-subtraction) ----
        const float4 ws0 = ((const float4*)warp_self)[0];
        const float4 ws1 = ((const float4*)warp_self)[1];
        const float s_self = ((ws0.x + ws0.y) + (ws0.z + ws0.w))
                           + ((ws1.x + ws1.y) + (ws1.z + ws1.w));
        const float z = s_self + s_nbr[lane];
        float e = (z >= 0.0f) ? z : 0.2f * z;
        e = (s_msk[lane] != 0.0f) ? e : -1e30f;
        const float ex = __expf(e);               // masked -> 0
        float sum = ex;
#pragma unroll
        for (int o = 16; o; o >>= 1)
            sum += __shfl_xor_sync(0xffffffffu, sum, o);
        const float att_lane = ex / sum;

        // ---- attention-weighted recombination from registers ----
        float4 h = make_float4(0.f, 0.f, 0.f, 0.f);
#pragma unroll
        for (int j = 0; j < SPW; ++j) {
            const float aL = __shfl_sync(0xffffffffu, att_lane, w * SPW + j);
            h.x += aL * v[j].x;
            h.y += aL * v[j].y;
            h.z += aL * v[j].z;
            h.w += aL * v[j].w;
        }

        hp[w * 32 + lane] = h;
        __syncthreads();

        // ---- cross-warp reduce (warp 0) + epilogue + store ----
        if (w == 0) {
            float4 acc = hp[lane];
#pragma unroll
            for (int i = 1; i < WARPS; ++i) {
                const float4 t = hp[i * 32 + lane];
                acc.x += t.x; acc.y += t.y; acc.z += t.z; acc.w += t.w;
            }
            acc.x = (acc.x > 0.f) ? acc.x : (__expf(acc.x) - 1.0f);
            acc.y = (acc.y > 0.f) ? acc.y : (__expf(acc.y) - 1.0f);
            acc.z = (acc.z > 0.f) ? acc.z : (__expf(acc.z) - 1.0f);
            acc.w = (acc.w > 0.f) ? acc.w : (__expf(acc.w) - 1.0f);
            ((float4*)(out + (size_t)m * F_DIM))[lane] = acc;
        }
    }
}

extern "C" void kernel_launch(void* const* d_in, const int* in_sizes, int n_in,
                              void* d_out, int out_size)
{
    const float* x = (const float*)d_in[0];
    const float* a = (const float*)d_in[1];
    float* out = (float*)d_out;

    // Shapes from element counts (capture-safe):
    //   in_sizes[0] = M*L*F, in_sizes[1] = F*(L+1), out_size = M*F
    const long long total = in_sizes[0];
    const int L = (int)(total / (long long)out_size);      // 32
    const int F = in_sizes[1] / (L + 1);                   // 128
    const int M = out_size / F;                            // 50000
    (void)L; (void)F;

    const int grid = (M + ROWS_PER_CTA - 1) / ROWS_PER_CTA;
    gat_row_kernel<<<grid, TPB>>>(x, a, out, M);
}